// round 14
// baseline (speedup 1.0000x reference)
#include <cuda_runtime.h>

#define N_    48
#define W_    16
#define X_    256
#define NW_   (N_ * W_)
#define SPLIT 6
#define GRID  (N_ * SPLIT)       // 288
#define CPB   (NW_ / SPLIT)      // 128 columns per block
#define INF_  1e30f
#define NCW   16                 // chunk warps
#define NWTOT 18                 // total warps (16 chunk + 2 positive)
#define BLK   (NWTOT * 32)       // 576 threads
#define FULL  0xffffffffu
#define CPW   (CPB / NCW)        // 8 columns per chunk warp
#define NGRP  9                  // arrival groups (288 = 9 * 32)
#define GRPSZ 32

// Partials laid out [chunk][anchor] -> flat idx = c*N_ + i (coalesced finish reads)
__device__ float    g_ltsum[GRID];
__device__ unsigned g_combo[GRID];     // hard | (accu<<16)
__device__ float    g_sumNeg[GRID];
__device__ float    g_minV[GRID];
__device__ int      g_minI[GRID];
// Per-anchor pos stats (single writer: the own-chunk block)
__device__ float    g_sumPos[N_];
__device__ float    g_maxV[N_];
__device__ int      g_maxI[N_];
// Two-level arrival counters (first level on distinct 128B lines)
__device__ int      g_cnt1[NGRP * 32];
__device__ int      g_cnt2;

__device__ __forceinline__ unsigned redux_add_u32(unsigned v) {
    unsigned r; asm volatile("redux.sync.add.u32 %0, %1, 0xffffffff;" : "=r"(r) : "r"(v)); return r;
}
__device__ __forceinline__ unsigned redux_min_u32(unsigned v) {
    unsigned r; asm volatile("redux.sync.min.u32 %0, %1, 0xffffffff;" : "=r"(r) : "r"(v)); return r;
}
__device__ __forceinline__ unsigned redux_max_u32(unsigned v) {
    unsigned r; asm volatile("redux.sync.max.u32 %0, %1, 0xffffffff;" : "=r"(r) : "r"(v)); return r;
}

__global__ void __launch_bounds__(BLK, 2) triplet_kernel(
    const float* __restrict__ emb,   // [N, W, X] f32
    const float* __restrict__ lab,   // [N, W]    f32 (0/1)
    float* __restrict__ out)         // [337]     f32
{
    const int bid  = blockIdx.x;
    const int i    = bid / SPLIT;          // anchor index
    const int c    = bid % SPLIT;          // column chunk
    const int col0 = c * CPB;
    const int tid  = threadIdx.x;
    const int lane = tid & 31;
    const int warp = tid >> 5;             // 0..17
    const bool hasOwn = (c == (i >> 3));   // own row lives in chunk i/8

    __shared__ float    s_own[W_];         // distances of positives 0..npos-1
    __shared__ float    s_tsum[NCW];
    __shared__ unsigned s_combo[NCW];
    __shared__ float    s_sn[NCW], s_minv[NCW];
    __shared__ int      s_mini[NCW];
    __shared__ float    s_sp[NCW], s_maxv[NCW];
    __shared__ int      s_maxi[NCW];
    __shared__ int      s_last;

    // labels straight to registers; ballot needs no distances
    const float labv = (lane < W_) ? lab[i * W_ + lane] : 0.f;
    const unsigned posmask = __ballot_sync(FULL, (lane < W_) && (labv > 0.f));
    const int npos = __popc(posmask);      // 1..15

    // anchor row in registers
    const float4* a4 = reinterpret_cast<const float4*>(emb + (size_t)i * W_ * X_);
    const float4 aA = a4[lane];
    const float4 aB = a4[lane + 32];

    float dcol[CPW];
    if (warp < NCW) {
        // ---- chunk warps: 8 column distances, 2 batches of 4 ----
        #pragma unroll
        for (int bt = 0; bt < 2; bt++) {
            float4 va[4], vb[4];
            #pragma unroll
            for (int u = 0; u < 4; u++) {
                const int j = col0 + warp + NCW * (4 * bt + u);
                const float4* f = reinterpret_cast<const float4*>(emb + (size_t)j * X_);
                va[u] = f[lane]; vb[u] = f[lane + 32];
            }
            float s[4];
            #pragma unroll
            for (int u = 0; u < 4; u++) {
                float acc = 0.f, d;
                d = aA.x - va[u].x; acc = fmaf(d, d, acc);
                d = aA.y - va[u].y; acc = fmaf(d, d, acc);
                d = aA.z - va[u].z; acc = fmaf(d, d, acc);
                d = aA.w - va[u].w; acc = fmaf(d, d, acc);
                d = aB.x - vb[u].x; acc = fmaf(d, d, acc);
                d = aB.y - vb[u].y; acc = fmaf(d, d, acc);
                d = aB.z - vb[u].z; acc = fmaf(d, d, acc);
                d = aB.w - vb[u].w; acc = fmaf(d, d, acc);
                s[u] = acc;
            }
            #pragma unroll
            for (int off = 16; off; off >>= 1) {
                #pragma unroll
                for (int u = 0; u < 4; u++)
                    s[u] += __shfl_xor_sync(FULL, s[u], off);
            }
            #pragma unroll
            for (int u = 0; u < 4; u++) dcol[4 * bt + u] = s[u];
        }
    } else {
        // ---- positive warps 16/17: distances of positives base..base+7 ----
        const int base = (warp - NCW) * 8;
        #pragma unroll
        for (int bt = 0; bt < 2; bt++) {
            const int p0 = base + 4 * bt;
            if (p0 >= npos) break;                 // warp-uniform
            float4 va[4], vb[4];
            #pragma unroll
            for (int u = 0; u < 4; u++) {
                const int p = p0 + u;
                if (p < npos) {                    // warp-uniform
                    const int wp = __fns(posmask, 0, p + 1);   // row of p-th positive
                    const float4* f = reinterpret_cast<const float4*>(
                        emb + (size_t)(i * W_ + wp) * X_);
                    va[u] = f[lane]; vb[u] = f[lane + 32];
                } else {
                    va[u] = make_float4(0.f, 0.f, 0.f, 0.f);
                    vb[u] = make_float4(0.f, 0.f, 0.f, 0.f);
                }
            }
            float s[4];
            #pragma unroll
            for (int u = 0; u < 4; u++) {
                float acc = 0.f, d;
                d = aA.x - va[u].x; acc = fmaf(d, d, acc);
                d = aA.y - va[u].y; acc = fmaf(d, d, acc);
                d = aA.z - va[u].z; acc = fmaf(d, d, acc);
                d = aA.w - va[u].w; acc = fmaf(d, d, acc);
                d = aB.x - vb[u].x; acc = fmaf(d, d, acc);
                d = aB.y - vb[u].y; acc = fmaf(d, d, acc);
                d = aB.z - vb[u].z; acc = fmaf(d, d, acc);
                d = aB.w - vb[u].w; acc = fmaf(d, d, acc);
                s[u] = acc;
            }
            #pragma unroll
            for (int off = 16; off; off >>= 1) {
                #pragma unroll
                for (int u = 0; u < 4; u++)
                    s[u] += __shfl_xor_sync(FULL, s[u], off);
            }
            if (lane == 0) {
                #pragma unroll
                for (int u = 0; u < 4; u++)
                    if (p0 + u < npos) s_own[p0 + u] = s[u];
            }
        }
    }
    __syncthreads();

    if (warp < NCW) {
        // dp: lane p directly reads the p-th positive's distance
        const bool isPairLane = (lane < npos);
        const float dp = isPairLane ? s_own[lane] : 0.f;

        // ---- pair phase over 8 register-resident distances ----
        float tsum = 0.f; int hard = 0, accu = 0;    // lane-parallel (lanes < npos <= 15)
        float sumNeg = 0.f;                          // uniform across lanes
        float minV = INF_; int minI = NW_;
        float sumPos = 0.f, maxV = -INF_; int maxI = NW_;

        if (hasOwn) {
            #pragma unroll
            for (int k = 0; k < CPW; k++) {
                const int j = col0 + warp + NCW * k;
                const float d = dcol[k];
                const int rel = j - i * W_;
                const bool inRow  = ((unsigned)rel < (unsigned)W_);
                const bool isPos  = inRow && ((posmask >> (rel & 31)) & 1u);
                const bool isAnch = (rel == 0);
                if (isPos) {
                    sumPos += d;
                    if (d > maxV) { maxV = d; maxI = j; }
                } else if (!isAnch) {
                    sumNeg += d;
                    if (d < minV) { minV = d; minI = j; }
                    if (isPairLane) {
                        float v = dp - d + 1.0f;      // diff + MARGIN
                        tsum += fmaxf(v, 0.f);
                        hard += (v > 1e-16f);
                        accu += (dp < d);
                    }
                }
            }
        } else {
            #pragma unroll
            for (int k = 0; k < CPW; k++) {
                const int j = col0 + warp + NCW * k;
                const float d = dcol[k];
                sumNeg += d;
                if (d < minV) { minV = d; minI = j; }
                if (isPairLane) {
                    float v = dp - d + 1.0f;
                    tsum += fmaxf(v, 0.f);
                    hard += (v > 1e-16f);
                    accu += (dp < d);
                }
            }
        }

        // ---- warp reduce lane-parallel quantities ----
        const unsigned combo = redux_add_u32((unsigned)hard | ((unsigned)accu << 16));
        #pragma unroll
        for (int off = 8; off; off >>= 1)
            tsum += __shfl_xor_sync(FULL, tsum, off);   // nonzero only in lanes 0..14
        if (lane == 0) {
            s_tsum[warp] = tsum;  s_combo[warp] = combo;
            s_sn[warp] = sumNeg;  s_minv[warp] = minV;  s_mini[warp] = minI;
            if (hasOwn) { s_sp[warp] = sumPos; s_maxv[warp] = maxV; s_maxi[warp] = maxI; }
        }
    }
    __syncthreads();

    // ---- block combine + publish (warp 0) ----
    if (warp == 0) {
        const bool v = (lane < NCW);
        float T  = v ? s_tsum[lane] : 0.f;
        float SN = v ? s_sn[lane]   : 0.f;
        float SP = (v && hasOwn) ? s_sp[lane] : 0.f;
        #pragma unroll
        for (int off = 8; off; off >>= 1) {           // partials in lanes 0..15
            T  += __shfl_xor_sync(FULL, T,  off);
            SN += __shfl_xor_sync(FULL, SN, off);
            SP += __shfl_xor_sync(FULL, SP, off);
        }
        const unsigned C = redux_add_u32(v ? s_combo[lane] : 0u);

        // min (value, then index) — distances >= 0 so float bits are ordered
        const unsigned mb = v ? __float_as_uint(s_minv[lane]) : __float_as_uint(INF_);
        const unsigned mm = redux_min_u32(mb);
        const unsigned mc = (v && mb == mm) ? (unsigned)s_mini[lane] : 0xffffffffu;
        const unsigned mi = redux_min_u32(mc);

        unsigned xm = 0u, xi = 0xffffffffu;
        if (hasOwn) {
            const float mxv = v ? s_maxv[lane] : -1.f;
            const bool  val = (mxv >= 0.f);
            const unsigned xb = val ? __float_as_uint(mxv) : 0u;
            xm = redux_max_u32(xb);
            const unsigned xc = (val && xb == xm) ? (unsigned)s_maxi[lane] : 0xffffffffu;
            xi = redux_min_u32(xc);
        }

        if (lane == 0) {
            const int idx = c * N_ + i;            // [chunk][anchor] layout
            g_ltsum[idx] = T;  g_combo[idx] = C;
            g_sumNeg[idx] = SN;
            g_minV[idx] = __uint_as_float(mm); g_minI[idx] = (int)mi;
            if (hasOwn) {
                g_sumPos[i] = SP;
                g_maxV[i] = __uint_as_float(xm); g_maxI[i] = (int)xi;
            }
            __threadfence();
            int lastf = 0;
            const int grp = bid >> 5;
            int a1 = atomicAdd(&g_cnt1[grp * 32], 1);
            if (a1 == GRPSZ - 1)
                lastf = (atomicAdd(&g_cnt2, 1) == NGRP - 1);
            s_last = lastf;
        }
    }
    __syncthreads();

    // ================= FINISH: last block, warps 0-2 =================
    if (s_last) {
        __threadfence();   // acquire all blocks' partials

        if (warp < 2) {
            // per-anchor outputs: warp0 -> anchors 0..31, warp1 -> 32..47
            const int a = warp * 32 + lane;
            if (a < N_) {
                float sn = 0.f; int acc = 0;
                float mv = INF_; int mi2 = NW_;
                #pragma unroll
                for (int cc = 0; cc < SPLIT; cc++) {
                    const int idx = cc * N_ + a;        // coalesced across lanes
                    sn  += ((volatile float*)g_sumNeg)[idx];
                    acc += (int)(((volatile unsigned*)g_combo)[idx] >> 16);
                    float nv = ((volatile float*)g_minV)[idx];
                    int   ni = ((volatile int*)g_minI)[idx];
                    if (nv < mv || (nv == mv && ni < mi2)) { mv = nv; mi2 = ni; }
                }
                const float sp  = ((volatile float*)g_sumPos)[a];
                const float MV2 = ((volatile float*)g_maxV)[a];
                const int   MI2 = ((volatile int*)g_maxI)[a];

                // labels via 4 x float4
                const float4* l4 = reinterpret_cast<const float4*>(lab + a * W_);
                float l[16];
                #pragma unroll
                for (int q = 0; q < 4; q++) {
                    float4 t = l4[q];
                    l[4*q+0] = t.x; l[4*q+1] = t.y; l[4*q+2] = t.z; l[4*q+3] = t.w;
                }
                int np = 0, ex = 0, pr = 0;
                #pragma unroll
                for (int w = 0; w < W_; w++) {
                    const bool isP = (l[w] > 0.f);
                    const int  col = a * W_ + w;
                    np += isP;
                    if (((w == 0) || isP) && col <= mi2) ex++;
                    if (isP && col <= MI2) pr++;
                }
                const int npext = np + ((l[0] > 0.f) ? 0 : 1);
                const float nn = (float)(NW_ - npext);
                const float npf = (float)np;
                const float npairs = npf * nn;

                out[1 + 0 * N_ + a] = MV2;                       // max_anchor2pos
                out[1 + 1 * N_ + a] = mv;                        // min_anchor2neg
                out[1 + 2 * N_ + a] = mv - MV2;                  // min_neg2pos
                out[1 + 3 * N_ + a] = (npf * sn - nn * sp) / npairs;  // avg_neg2pos
                out[1 + 4 * N_ + a] = (float)(mi2 - ex);         // neg_idx
                out[1 + 5 * N_ + a] = (float)(pr - 1);           // pos_idx
                out[1 + 6 * N_ + a] = (float)acc / npairs;       // accu_ratio
            }
        } else if (warp == 2) {
            // global loss over 288 partials, lane-strided fixed mapping
            float s = 0.f, h = 0.f;
            for (int k = lane; k < GRID; k += 32) {
                s += ((volatile float*)g_ltsum)[k];
                h += (float)(((volatile unsigned*)g_combo)[k] & 0xffffu);
            }
            #pragma unroll
            for (int off = 16; off; off >>= 1) {
                s += __shfl_xor_sync(FULL, s, off);
                h += __shfl_xor_sync(FULL, h, off);
            }
            if (lane == 0) {
                out[0] = s / (h + 1e-16f);
                g_cnt2 = 0;    // reset for next graph replay
            }
            if (lane < NGRP) g_cnt1[lane * 32] = 0;
        }
    }
}

extern "C" void kernel_launch(void* const* d_in, const int* in_sizes, int n_in,
                              void* d_out, int out_size) {
    const float* emb = (const float*)d_in[0];   // pred_embeddings [48,16,256]
    const float* lab = (const float*)d_in[1];   // pos_neg_label  [48,16]
    float* out = (float*)d_out;                 // 337 floats

    triplet_kernel<<<GRID, BLK>>>(emb, lab, out);
}

// round 15
// speedup vs baseline: 1.0045x; 1.0045x over previous
#include <cuda_runtime.h>

#define N_    48
#define W_    16
#define X_    256
#define NW_   (N_ * W_)
#define SPLIT 6
#define GRID  (N_ * SPLIT)       // 288
#define CPB   (NW_ / SPLIT)      // 128 columns per block
#define INF_  1e30f
#define NWARP 16
#define BLK   (NWARP * 32)       // 512 threads
#define FULL  0xffffffffu
#define CPW   (CPB / NWARP)      // 8 columns per warp
#define NGRP  9                  // arrival groups (288 = 9 * 32)
#define GRPSZ 32

// Partials laid out [chunk][anchor] -> flat idx = c*N_ + i (coalesced finish reads)
__device__ float    g_ltsum[GRID];
__device__ unsigned g_combo[GRID];     // hard | (accu<<16)
__device__ float    g_sumNeg[GRID];
__device__ float    g_minV[GRID];
__device__ int      g_minI[GRID];
// Per-anchor pos stats (single writer: the own-chunk block)
__device__ float    g_sumPos[N_];
__device__ float    g_maxV[N_];
__device__ int      g_maxI[N_];
// Two-level arrival counters (first level on distinct 128B lines)
__device__ int      g_cnt1[NGRP * 32];
__device__ int      g_cnt2;

__device__ __forceinline__ unsigned redux_add_u32(unsigned v) {
    unsigned r; asm volatile("redux.sync.add.u32 %0, %1, 0xffffffff;" : "=r"(r) : "r"(v)); return r;
}
__device__ __forceinline__ unsigned redux_min_u32(unsigned v) {
    unsigned r; asm volatile("redux.sync.min.u32 %0, %1, 0xffffffff;" : "=r"(r) : "r"(v)); return r;
}
__device__ __forceinline__ unsigned redux_max_u32(unsigned v) {
    unsigned r; asm volatile("redux.sync.max.u32 %0, %1, 0xffffffff;" : "=r"(r) : "r"(v)); return r;
}

__global__ void __launch_bounds__(BLK, 2) triplet_kernel(
    const float* __restrict__ emb,   // [N, W, X] f32
    const float* __restrict__ lab,   // [N, W]    f32 (0/1)
    float* __restrict__ out)         // [337]     f32
{
    const int bid  = blockIdx.x;
    const int i    = bid / SPLIT;          // anchor index
    const int c    = bid % SPLIT;          // column chunk
    const int col0 = c * CPB;
    const int tid  = threadIdx.x;
    const int lane = tid & 31;
    const int warp = tid >> 5;
    const bool hasOwn = (c == (i >> 3));   // own row lives in chunk i/8

    __shared__ float    s_own[W_];
    __shared__ float    s_tsum[NWARP];
    __shared__ unsigned s_combo[NWARP];
    __shared__ float    s_sn[NWARP], s_minv[NWARP];
    __shared__ int      s_mini[NWARP];
    __shared__ float    s_sp[NWARP], s_maxv[NWARP];
    __shared__ int      s_maxi[NWARP];
    __shared__ int      s_last;

    // labels straight to registers
    const float labv = (lane < W_) ? lab[i * W_ + lane] : 0.f;

    // anchor row in registers
    const float4* a4 = reinterpret_cast<const float4*>(emb + (size_t)i * W_ * X_);
    const float4 aA = a4[lane];
    const float4 aB = a4[lane + 32];

    // ---- own-row distance: warp w computes own column w ----
    {
        const float4* f = reinterpret_cast<const float4*>(emb + (size_t)(i * W_ + warp) * X_);
        float4 va = f[lane], vb = f[lane + 32];
        float s = 0.f, d;
        d = aA.x - va.x; s = fmaf(d, d, s);
        d = aA.y - va.y; s = fmaf(d, d, s);
        d = aA.z - va.z; s = fmaf(d, d, s);
        d = aA.w - va.w; s = fmaf(d, d, s);
        d = aB.x - vb.x; s = fmaf(d, d, s);
        d = aB.y - vb.y; s = fmaf(d, d, s);
        d = aB.z - vb.z; s = fmaf(d, d, s);
        d = aB.w - vb.w; s = fmaf(d, d, s);
        #pragma unroll
        for (int off = 16; off; off >>= 1) s += __shfl_xor_sync(FULL, s, off);
        if (lane == 0) s_own[warp] = s;
    }

    // ---- 8 chunk-column distances, 2 batches of 4 ----
    float dcol[CPW];
    #pragma unroll
    for (int bt = 0; bt < 2; bt++) {
        float4 va[4], vb[4];
        #pragma unroll
        for (int u = 0; u < 4; u++) {
            const int j = col0 + warp + NWARP * (4 * bt + u);
            const float4* f = reinterpret_cast<const float4*>(emb + (size_t)j * X_);
            va[u] = f[lane]; vb[u] = f[lane + 32];
        }
        float s[4];
        #pragma unroll
        for (int u = 0; u < 4; u++) {
            float acc = 0.f, d;
            d = aA.x - va[u].x; acc = fmaf(d, d, acc);
            d = aA.y - va[u].y; acc = fmaf(d, d, acc);
            d = aA.z - va[u].z; acc = fmaf(d, d, acc);
            d = aA.w - va[u].w; acc = fmaf(d, d, acc);
            d = aB.x - vb[u].x; acc = fmaf(d, d, acc);
            d = aB.y - vb[u].y; acc = fmaf(d, d, acc);
            d = aB.z - vb[u].z; acc = fmaf(d, d, acc);
            d = aB.w - vb[u].w; acc = fmaf(d, d, acc);
            s[u] = acc;
        }
        #pragma unroll
        for (int off = 16; off; off >>= 1) {
            #pragma unroll
            for (int u = 0; u < 4; u++)
                s[u] += __shfl_xor_sync(FULL, s[u], off);
        }
        #pragma unroll
        for (int u = 0; u < 4; u++) dcol[4 * bt + u] = s[u];
    }
    __syncthreads();

    // ---- positive compaction: lane p gets distance of positive p ----
    const float ownv = (lane < W_) ? s_own[lane] : 0.f;
    const unsigned posmask = __ballot_sync(FULL, (lane < W_) && (labv > 0.f));
    const int npos = __popc(posmask);
    int srcl = __fns(posmask, 0, lane + 1);
    if (srcl < 0 || srcl > 31) srcl = 0;
    const float dp = __shfl_sync(FULL, ownv, srcl);
    const bool isPairLane = (lane < npos);

    // ---- pair phase over 8 register-resident distances ----
    float tsum = 0.f; int hard = 0, accu = 0;        // lane-parallel
    float sumNeg = 0.f;                              // uniform across lanes
    float minV = INF_; int minI = NW_;
    float sumPos = 0.f, maxV = -INF_; int maxI = NW_;

    if (hasOwn) {
        #pragma unroll
        for (int k = 0; k < CPW; k++) {
            const int j = col0 + warp + NWARP * k;
            const float d = dcol[k];
            const int rel = j - i * W_;
            const bool inRow  = ((unsigned)rel < (unsigned)W_);
            const bool isPos  = inRow && ((posmask >> (rel & 31)) & 1u);
            const bool isAnch = (rel == 0);
            if (isPos) {
                sumPos += d;
                if (d > maxV) { maxV = d; maxI = j; }
            } else if (!isAnch) {
                sumNeg += d;
                if (d < minV) { minV = d; minI = j; }
                if (isPairLane) {
                    float v = dp - d + 1.0f;          // diff + MARGIN
                    tsum += fmaxf(v, 0.f);
                    hard += (v > 1e-16f);
                    accu += (dp < d);
                }
            }
        }
    } else {
        #pragma unroll
        for (int k = 0; k < CPW; k++) {
            const int j = col0 + warp + NWARP * k;
            const float d = dcol[k];
            sumNeg += d;
            if (d < minV) { minV = d; minI = j; }
            if (isPairLane) {
                float v = dp - d + 1.0f;
                tsum += fmaxf(v, 0.f);
                hard += (v > 1e-16f);
                accu += (dp < d);
            }
        }
    }

    // ---- warp reduce lane-parallel quantities ----
    const unsigned combo = redux_add_u32((unsigned)hard | ((unsigned)accu << 16));
    #pragma unroll
    for (int off = 16; off; off >>= 1)
        tsum += __shfl_xor_sync(FULL, tsum, off);
    if (lane == 0) {
        s_tsum[warp] = tsum;  s_combo[warp] = combo;
        s_sn[warp] = sumNeg;  s_minv[warp] = minV;  s_mini[warp] = minI;
        if (hasOwn) { s_sp[warp] = sumPos; s_maxv[warp] = maxV; s_maxi[warp] = maxI; }
    }
    __syncthreads();

    // ---- block combine + publish (warp 0) ----
    if (warp == 0) {
        const bool v = (lane < NWARP);
        float T  = v ? s_tsum[lane] : 0.f;
        float SN = v ? s_sn[lane]   : 0.f;
        float SP = (v && hasOwn) ? s_sp[lane] : 0.f;
        #pragma unroll
        for (int off = 16; off; off >>= 1) {
            T  += __shfl_xor_sync(FULL, T,  off);
            SN += __shfl_xor_sync(FULL, SN, off);
            SP += __shfl_xor_sync(FULL, SP, off);
        }
        const unsigned C = redux_add_u32(v ? s_combo[lane] : 0u);

        // min (value, then index) — distances >= 0 so float bits are ordered
        const unsigned mb = v ? __float_as_uint(s_minv[lane]) : __float_as_uint(INF_);
        const unsigned mm = redux_min_u32(mb);
        const unsigned mc = (v && mb == mm) ? (unsigned)s_mini[lane] : 0xffffffffu;
        const unsigned mi = redux_min_u32(mc);

        unsigned xm = 0u, xi = 0xffffffffu;
        if (hasOwn) {
            const float mxv = v ? s_maxv[lane] : -1.f;
            const bool  val = (mxv >= 0.f);
            const unsigned xb = val ? __float_as_uint(mxv) : 0u;
            xm = redux_max_u32(xb);
            const unsigned xc = (val && xb == xm) ? (unsigned)s_maxi[lane] : 0xffffffffu;
            xi = redux_min_u32(xc);
        }

        if (lane == 0) {
            const int idx = c * N_ + i;            // [chunk][anchor] layout
            g_ltsum[idx] = T;  g_combo[idx] = C;
            g_sumNeg[idx] = SN;
            g_minV[idx] = __uint_as_float(mm); g_minI[idx] = (int)mi;
            if (hasOwn) {
                g_sumPos[i] = SP;
                g_maxV[i] = __uint_as_float(xm); g_maxI[i] = (int)xi;
            }
            __threadfence();
            int lastf = 0;
            const int grp = bid >> 5;
            int a1 = atomicAdd(&g_cnt1[grp * 32], 1);
            if (a1 == GRPSZ - 1)
                lastf = (atomicAdd(&g_cnt2, 1) == NGRP - 1);
            s_last = lastf;
        }
    }
    __syncthreads();

    // ================= FINISH: last block, all warps participate =================
    if (s_last) {
        __threadfence();   // acquire all blocks' partials

        if (warp < 2) {
            // per-anchor outputs: warp0 -> anchors 0..31, warp1 -> 32..47
            const int a = warp * 32 + lane;
            if (a < N_) {
                float sn = 0.f; int acc = 0;
                float mv = INF_; int mi2 = NW_;
                #pragma unroll
                for (int cc = 0; cc < SPLIT; cc++) {
                    const int idx = cc * N_ + a;        // coalesced across lanes
                    sn  += ((volatile float*)g_sumNeg)[idx];
                    acc += (int)(((volatile unsigned*)g_combo)[idx] >> 16);
                    float nv = ((volatile float*)g_minV)[idx];
                    int   ni = ((volatile int*)g_minI)[idx];
                    if (nv < mv || (nv == mv && ni < mi2)) { mv = nv; mi2 = ni; }
                }
                const float sp  = ((volatile float*)g_sumPos)[a];
                const float MV2 = ((volatile float*)g_maxV)[a];
                const int   MI2 = ((volatile int*)g_maxI)[a];

                // labels via 4 x float4
                const float4* l4 = reinterpret_cast<const float4*>(lab + a * W_);
                float l[16];
                #pragma unroll
                for (int q = 0; q < 4; q++) {
                    float4 t = l4[q];
                    l[4*q+0] = t.x; l[4*q+1] = t.y; l[4*q+2] = t.z; l[4*q+3] = t.w;
                }
                int np = 0, ex = 0, pr = 0;
                #pragma unroll
                for (int w = 0; w < W_; w++) {
                    const bool isP = (l[w] > 0.f);
                    const int  col = a * W_ + w;
                    np += isP;
                    if (((w == 0) || isP) && col <= mi2) ex++;
                    if (isP && col <= MI2) pr++;
                }
                const int npext = np + ((l[0] > 0.f) ? 0 : 1);
                const float nn = (float)(NW_ - npext);
                const float npf = (float)np;
                const float npairs = npf * nn;

                out[1 + 0 * N_ + a] = MV2;                       // max_anchor2pos
                out[1 + 1 * N_ + a] = mv;                        // min_anchor2neg
                out[1 + 2 * N_ + a] = mv - MV2;                  // min_neg2pos
                out[1 + 3 * N_ + a] = (npf * sn - nn * sp) / npairs;  // avg_neg2pos
                out[1 + 4 * N_ + a] = (float)(mi2 - ex);         // neg_idx
                out[1 + 5 * N_ + a] = (float)(pr - 1);           // pos_idx
                out[1 + 6 * N_ + a] = (float)acc / npairs;       // accu_ratio
            }
        } else if (warp == 2) {
            // global loss over 288 partials, lane-strided fixed mapping
            float s = 0.f, h = 0.f;
            for (int k = lane; k < GRID; k += 32) {
                s += ((volatile float*)g_ltsum)[k];
                h += (float)(((volatile unsigned*)g_combo)[k] & 0xffffu);
            }
            #pragma unroll
            for (int off = 16; off; off >>= 1) {
                s += __shfl_xor_sync(FULL, s, off);
                h += __shfl_xor_sync(FULL, h, off);
            }
            if (lane == 0) {
                out[0] = s / (h + 1e-16f);
                g_cnt2 = 0;    // reset for next graph replay
            }
            if (lane < NGRP) g_cnt1[lane * 32] = 0;
        }
    }
}

extern "C" void kernel_launch(void* const* d_in, const int* in_sizes, int n_in,
                              void* d_out, int out_size) {
    const float* emb = (const float*)d_in[0];   // pred_embeddings [48,16,256]
    const float* lab = (const float*)d_in[1];   // pos_neg_label  [48,16]
    float* out = (float*)d_out;                 // 337 floats

    triplet_kernel<<<GRID, BLK>>>(emb, lab, out);
}

// round 16
// speedup vs baseline: 1.0976x; 1.0927x over previous
#include <cuda_runtime.h>

#define N_    48
#define W_    16
#define X_    256
#define NW_   (N_ * W_)
#define SPLIT 6
#define GRID  (N_ * SPLIT)       // 288
#define CPB   (NW_ / SPLIT)      // 128 columns per block
#define INF_  1e30f
#define NWARP 16
#define BLK   (NWARP * 32)       // 512 threads
#define FULL  0xffffffffu
#define CPW   (CPB / NWARP)      // 8 columns per warp
#define NGRP  9                  // arrival groups (288 = 9 * 32)
#define GRPSZ 32

// Partials laid out [chunk][anchor] -> flat idx = c*N_ + i (coalesced finish reads)
__device__ float    g_ltsum[GRID];
__device__ unsigned g_combo[GRID];     // hard | (accu<<16)
__device__ float    g_sumNeg[GRID];
__device__ float    g_minV[GRID];
__device__ int      g_minI[GRID];
// Per-anchor pos stats (single writer: the own-chunk block)
__device__ float    g_sumPos[N_];
__device__ float    g_maxV[N_];
__device__ int      g_maxI[N_];
// Two-level arrival counters (first level on distinct 128B lines)
__device__ int      g_cnt1[NGRP * 32];
__device__ int      g_cnt2;

__device__ __forceinline__ unsigned redux_add_u32(unsigned v) {
    unsigned r; asm volatile("redux.sync.add.u32 %0, %1, 0xffffffff;" : "=r"(r) : "r"(v)); return r;
}
__device__ __forceinline__ unsigned redux_min_u32(unsigned v) {
    unsigned r; asm volatile("redux.sync.min.u32 %0, %1, 0xffffffff;" : "=r"(r) : "r"(v)); return r;
}
__device__ __forceinline__ unsigned redux_max_u32(unsigned v) {
    unsigned r; asm volatile("redux.sync.max.u32 %0, %1, 0xffffffff;" : "=r"(r) : "r"(v)); return r;
}

__global__ void __launch_bounds__(BLK, 2) triplet_kernel(
    const float* __restrict__ emb,   // [N, W, X] f32
    const float* __restrict__ lab,   // [N, W]    f32 (0/1)
    float* __restrict__ out)         // [337]     f32
{
    const int bid  = blockIdx.x;
    const int i    = bid / SPLIT;          // anchor index
    const int c    = bid % SPLIT;          // column chunk
    const int col0 = c * CPB;
    const int tid  = threadIdx.x;
    const int lane = tid & 31;
    const int warp = tid >> 5;
    const bool hasOwn = (c == (i >> 3));   // own row lives in chunk i/8

    __shared__ float    s_own[W_];
    __shared__ float    s_tsum[NWARP];
    __shared__ unsigned s_combo[NWARP];
    __shared__ float    s_sn[NWARP], s_minv[NWARP];
    __shared__ int      s_mini[NWARP];
    __shared__ float    s_sp[NWARP], s_maxv[NWARP];
    __shared__ int      s_maxi[NWARP];
    __shared__ int      s_last;

    // labels + positive compaction FIRST (label-only, overlaps the load window)
    const float labv = (lane < W_) ? lab[i * W_ + lane] : 0.f;
    const unsigned posmask = __ballot_sync(FULL, (lane < W_) && (labv > 0.f));
    const int npos = __popc(posmask);
    int srcl = __fns(posmask, 0, lane + 1);      // row of the (lane+1)-th positive
    if (srcl < 0 || srcl > 31) srcl = 0;
    const bool isPairLane = (lane < npos);

    // anchor row in registers
    const float4* a4 = reinterpret_cast<const float4*>(emb + (size_t)i * W_ * X_);
    const float4 aA = a4[lane];
    const float4 aB = a4[lane + 32];

    // ---- own-row distance: warp w computes own column w ----
    {
        const float4* f = reinterpret_cast<const float4*>(emb + (size_t)(i * W_ + warp) * X_);
        float4 va = f[lane], vb = f[lane + 32];
        float s = 0.f, d;
        d = aA.x - va.x; s = fmaf(d, d, s);
        d = aA.y - va.y; s = fmaf(d, d, s);
        d = aA.z - va.z; s = fmaf(d, d, s);
        d = aA.w - va.w; s = fmaf(d, d, s);
        d = aB.x - vb.x; s = fmaf(d, d, s);
        d = aB.y - vb.y; s = fmaf(d, d, s);
        d = aB.z - vb.z; s = fmaf(d, d, s);
        d = aB.w - vb.w; s = fmaf(d, d, s);
        #pragma unroll
        for (int off = 16; off; off >>= 1) s += __shfl_xor_sync(FULL, s, off);
        if (lane == 0) s_own[warp] = s;
    }

    // ---- 8 chunk-column distances, 2 batches of 4 ----
    float dcol[CPW];
    #pragma unroll
    for (int bt = 0; bt < 2; bt++) {
        float4 va[4], vb[4];
        #pragma unroll
        for (int u = 0; u < 4; u++) {
            const int j = col0 + warp + NWARP * (4 * bt + u);
            const float4* f = reinterpret_cast<const float4*>(emb + (size_t)j * X_);
            va[u] = f[lane]; vb[u] = f[lane + 32];
        }
        float s[4];
        #pragma unroll
        for (int u = 0; u < 4; u++) {
            float acc = 0.f, d;
            d = aA.x - va[u].x; acc = fmaf(d, d, acc);
            d = aA.y - va[u].y; acc = fmaf(d, d, acc);
            d = aA.z - va[u].z; acc = fmaf(d, d, acc);
            d = aA.w - va[u].w; acc = fmaf(d, d, acc);
            d = aB.x - vb[u].x; acc = fmaf(d, d, acc);
            d = aB.y - vb[u].y; acc = fmaf(d, d, acc);
            d = aB.z - vb[u].z; acc = fmaf(d, d, acc);
            d = aB.w - vb[u].w; acc = fmaf(d, d, acc);
            s[u] = acc;
        }
        #pragma unroll
        for (int off = 16; off; off >>= 1) {
            #pragma unroll
            for (int u = 0; u < 4; u++)
                s[u] += __shfl_xor_sync(FULL, s[u], off);
        }
        #pragma unroll
        for (int u = 0; u < 4; u++) dcol[4 * bt + u] = s[u];
    }
    __syncthreads();

    // lane p reads the p-th positive's distance directly
    const float dp = s_own[srcl];

    // ---- pair phase over 8 register-resident distances ----
    float tsum = 0.f; int hard = 0, accu = 0;        // lane-parallel
    float sumNeg = 0.f;                              // uniform across lanes
    float minV = INF_; int minI = NW_;
    float sumPos = 0.f, maxV = -INF_; int maxI = NW_;

    if (hasOwn) {
        #pragma unroll
        for (int k = 0; k < CPW; k++) {
            const int j = col0 + warp + NWARP * k;
            const float d = dcol[k];
            const int rel = j - i * W_;
            const bool inRow  = ((unsigned)rel < (unsigned)W_);
            const bool isPos  = inRow && ((posmask >> (rel & 31)) & 1u);
            const bool isAnch = (rel == 0);
            if (isPos) {
                sumPos += d;
                if (d > maxV) { maxV = d; maxI = j; }
            } else if (!isAnch) {
                sumNeg += d;
                if (d < minV) { minV = d; minI = j; }
                if (isPairLane) {
                    float v = dp - d + 1.0f;          // diff + MARGIN
                    tsum += fmaxf(v, 0.f);
                    hard += (v > 1e-16f);
                    accu += (dp < d);
                }
            }
        }
    } else {
        #pragma unroll
        for (int k = 0; k < CPW; k++) {
            const int j = col0 + warp + NWARP * k;
            const float d = dcol[k];
            sumNeg += d;
            if (d < minV) { minV = d; minI = j; }
            if (isPairLane) {
                float v = dp - d + 1.0f;
                tsum += fmaxf(v, 0.f);
                hard += (v > 1e-16f);
                accu += (dp < d);
            }
        }
    }

    // ---- warp reduce lane-parallel quantities ----
    const unsigned combo = redux_add_u32((unsigned)hard | ((unsigned)accu << 16));
    #pragma unroll
    for (int off = 16; off; off >>= 1)
        tsum += __shfl_xor_sync(FULL, tsum, off);
    if (lane == 0) {
        s_tsum[warp] = tsum;  s_combo[warp] = combo;
        s_sn[warp] = sumNeg;  s_minv[warp] = minV;  s_mini[warp] = minI;
        if (hasOwn) { s_sp[warp] = sumPos; s_maxv[warp] = maxV; s_maxi[warp] = maxI; }
    }
    __syncthreads();

    // ---- block combine + publish (warp 0) ----
    if (warp == 0) {
        const bool v = (lane < NWARP);
        float T  = v ? s_tsum[lane] : 0.f;
        float SN = v ? s_sn[lane]   : 0.f;
        float SP = (v && hasOwn) ? s_sp[lane] : 0.f;
        #pragma unroll
        for (int off = 16; off; off >>= 1) {
            T  += __shfl_xor_sync(FULL, T,  off);
            SN += __shfl_xor_sync(FULL, SN, off);
            SP += __shfl_xor_sync(FULL, SP, off);
        }
        const unsigned C = redux_add_u32(v ? s_combo[lane] : 0u);

        // min (value, then index) — distances >= 0 so float bits are ordered
        const unsigned mb = v ? __float_as_uint(s_minv[lane]) : __float_as_uint(INF_);
        const unsigned mm = redux_min_u32(mb);
        const unsigned mc = (v && mb == mm) ? (unsigned)s_mini[lane] : 0xffffffffu;
        const unsigned mi = redux_min_u32(mc);

        unsigned xm = 0u, xi = 0xffffffffu;
        if (hasOwn) {
            const float mxv = v ? s_maxv[lane] : -1.f;
            const bool  val = (mxv >= 0.f);
            const unsigned xb = val ? __float_as_uint(mxv) : 0u;
            xm = redux_max_u32(xb);
            const unsigned xc = (val && xb == xm) ? (unsigned)s_maxi[lane] : 0xffffffffu;
            xi = redux_min_u32(xc);
        }

        if (lane == 0) {
            const int idx = c * N_ + i;            // [chunk][anchor] layout
            g_ltsum[idx] = T;  g_combo[idx] = C;
            g_sumNeg[idx] = SN;
            g_minV[idx] = __uint_as_float(mm); g_minI[idx] = (int)mi;
            if (hasOwn) {
                g_sumPos[i] = SP;
                g_maxV[i] = __uint_as_float(xm); g_maxI[i] = (int)xi;
            }
            __threadfence();
            int lastf = 0;
            const int grp = bid >> 5;
            int a1 = atomicAdd(&g_cnt1[grp * 32], 1);
            if (a1 == GRPSZ - 1)
                lastf = (atomicAdd(&g_cnt2, 1) == NGRP - 1);
            s_last = lastf;
        }
    }
    __syncthreads();

    // ================= FINISH: last block, warps 0-2 =================
    if (s_last) {
        __threadfence();   // acquire all blocks' partials

        if (warp < 2) {
            // per-anchor outputs: warp0 -> anchors 0..31, warp1 -> 32..47
            const int a = warp * 32 + lane;
            if (a < N_) {
                float sn = 0.f; int acc = 0;
                float mv = INF_; int mi2 = NW_;
                #pragma unroll
                for (int cc = 0; cc < SPLIT; cc++) {
                    const int idx = cc * N_ + a;        // coalesced across lanes
                    sn  += ((volatile float*)g_sumNeg)[idx];
                    acc += (int)(((volatile unsigned*)g_combo)[idx] >> 16);
                    float nv = ((volatile float*)g_minV)[idx];
                    int   ni = ((volatile int*)g_minI)[idx];
                    if (nv < mv || (nv == mv && ni < mi2)) { mv = nv; mi2 = ni; }
                }
                const float sp  = ((volatile float*)g_sumPos)[a];
                const float MV2 = ((volatile float*)g_maxV)[a];
                const int   MI2 = ((volatile int*)g_maxI)[a];

                // labels via 4 x float4
                const float4* l4 = reinterpret_cast<const float4*>(lab + a * W_);
                float l[16];
                #pragma unroll
                for (int q = 0; q < 4; q++) {
                    float4 t = l4[q];
                    l[4*q+0] = t.x; l[4*q+1] = t.y; l[4*q+2] = t.z; l[4*q+3] = t.w;
                }
                int np = 0, ex = 0, pr = 0;
                #pragma unroll
                for (int w = 0; w < W_; w++) {
                    const bool isP = (l[w] > 0.f);
                    const int  col = a * W_ + w;
                    np += isP;
                    if (((w == 0) || isP) && col <= mi2) ex++;
                    if (isP && col <= MI2) pr++;
                }
                const int npext = np + ((l[0] > 0.f) ? 0 : 1);
                const float nn = (float)(NW_ - npext);
                const float npf = (float)np;
                const float npairs = npf * nn;

                out[1 + 0 * N_ + a] = MV2;                       // max_anchor2pos
                out[1 + 1 * N_ + a] = mv;                        // min_anchor2neg
                out[1 + 2 * N_ + a] = mv - MV2;                  // min_neg2pos
                out[1 + 3 * N_ + a] = (npf * sn - nn * sp) / npairs;  // avg_neg2pos
                out[1 + 4 * N_ + a] = (float)(mi2 - ex);         // neg_idx
                out[1 + 5 * N_ + a] = (float)(pr - 1);           // pos_idx
                out[1 + 6 * N_ + a] = (float)acc / npairs;       // accu_ratio
            }
        } else if (warp == 2) {
            // global loss over 288 partials, lane-strided fixed mapping
            float s = 0.f, h = 0.f;
            for (int k = lane; k < GRID; k += 32) {
                s += ((volatile float*)g_ltsum)[k];
                h += (float)(((volatile unsigned*)g_combo)[k] & 0xffffu);
            }
            #pragma unroll
            for (int off = 16; off; off >>= 1) {
                s += __shfl_xor_sync(FULL, s, off);
                h += __shfl_xor_sync(FULL, h, off);
            }
            if (lane == 0) {
                out[0] = s / (h + 1e-16f);
                g_cnt2 = 0;    // reset for next graph replay
            }
            if (lane < NGRP) g_cnt1[lane * 32] = 0;
        }
    }
}

extern "C" void kernel_launch(void* const* d_in, const int* in_sizes, int n_in,
                              void* d_out, int out_size) {
    const float* emb = (const float*)d_in[0];   // pred_embeddings [48,16,256]
    const float* lab = (const float*)d_in[1];   // pos_neg_label  [48,16]
    float* out = (float*)d_out;                 // 337 floats

    triplet_kernel<<<GRID, BLK>>>(emb, lab, out);
}